// round 5
// baseline (speedup 1.0000x reference)
#include <cuda_runtime.h>
#include <math.h>

#define NB 16
#define NT 256
#define NC 64
#define NF 128
#define NGO 32
#define NH 32
#define TCHUNK 8

typedef unsigned long long u64;

// ---------------- packed f32x2 helpers ----------------
__device__ __forceinline__ u64 PK(float x, float y) {
    u64 r;
    asm("mov.b64 %0, {%1,%2};" : "=l"(r) : "f"(x), "f"(y));
    return r;
}
__device__ __forceinline__ float2 UPK(u64 v) {
    float2 f;
    asm("mov.b64 {%0,%1}, %2;" : "=f"(f.x), "=f"(f.y) : "l"(v));
    return f;
}
__device__ __forceinline__ u64 FFMA2(u64 a, u64 b, u64 c) {
    u64 d;
    asm("fma.rn.f32x2 %0, %1, %2, %3;" : "=l"(d) : "l"(a), "l"(b), "l"(c));
    return d;
}
__device__ __forceinline__ float HSUM(u64 v) {
    float2 f = UPK(v);
    return f.x + f.y;
}
__device__ __forceinline__ float fast_tanh(float x) {
    float e = __expf(2.0f * x);
    return 1.0f - __fdividef(2.0f, e + 1.0f);
}
__device__ __forceinline__ float fast_sig(float x) {
    return 1.0f / (1.0f + __expf(-x));
}

// ---------------- scratch ----------------
__device__ float g_sm[NC * NF];
__device__ float g_A[NB * NC * NC];
__device__ u64 g_um[NB * NC];
__device__ unsigned char g_amask[NB * NC * NC];
__device__ float g_Wh[NB * NT * NGO * NC];   // TRANSPOSED: [bt][j][c]
__device__ float g_s1[NB * NT * NC];
__device__ float g_s2[NB * NT * NC];
__device__ float g_hp[NB * NT * NH];
__device__ float g_gx[2 * NB * NT * 4 * NH];
__device__ float g_hl[NB * NT * 2 * NH];
__device__ float g_sc[NB * NT];

// ---------------- kernel 0: row softmax of spectral_w ----------------
__global__ void k_sm(const float* __restrict__ sw) {
    int c = blockIdx.x, f = threadIdx.x;
    float v = sw[c * NF + f];
    __shared__ float rm[4], rs[4];
    int lane = f & 31, w = f >> 5;
    float m = v;
#pragma unroll
    for (int o = 16; o; o >>= 1) m = fmaxf(m, __shfl_xor_sync(0xffffffffu, m, o));
    if (lane == 0) rm[w] = m;
    __syncthreads();
    m = fmaxf(fmaxf(rm[0], rm[1]), fmaxf(rm[2], rm[3]));
    float e = __expf(v - m);
    float s = e;
#pragma unroll
    for (int o = 16; o; o >>= 1) s += __shfl_xor_sync(0xffffffffu, s, o);
    if (lane == 0) rs[w] = s;
    __syncthreads();
    s = rs[0] + rs[1] + rs[2] + rs[3];
    g_sm[c * NF + f] = e / s;
}

// zero g_A in two halves (also positions k1 as the 4th launch for ncu)
__global__ void k_zeroA(int half) {
    int i = half * (NB * NC * NC / 2) + blockIdx.x * blockDim.x + threadIdx.x;
    g_A[i] = 0.0f;
}

// ---------------- kernel 1: spectral weight + Gram->A + WhT + s1/s2 ----------------
extern __shared__ float sh1[];
__global__ void __launch_bounds__(256, 2) k1(const float* __restrict__ x,
                                             const float* __restrict__ gatW,
                                             const float* __restrict__ gata) {
    float* xw   = sh1;                    // 64 x 132
    float* swT  = sh1 + 64 * 132;         // 32 x 132 (transposed gat_W)
    float* invn = swT + 32 * 132;         // 64

    const int b  = blockIdx.x / (NT / TCHUNK);
    const int t0 = (blockIdx.x % (NT / TCHUNK)) * TCHUNK;
    const int tid = threadIdx.x;

    for (int i = tid; i < NF * NGO; i += 256) {
        int f = i >> 5, j = i & 31;
        swT[j * 132 + f] = gatW[i];
    }

    // triangle 4x4-tile mapping (136 tiles)
    int ci = -1, di = -1;
    {
        int u = tid;
        for (int r = 0; r < 16; r++) {
            int len = 16 - r;
            if (u < len) { ci = r; di = r + u; break; }
            u -= len;
        }
        if (tid >= 136) ci = -1;
    }
    const int r0 = (ci >= 0) ? ci * 4 : 0;
    const int c0 = (ci >= 0) ? di * 4 : 0;

    const int cW = tid >> 2, q = tid & 3, o0 = q * 8;

    float acc[16];
#pragma unroll
    for (int i = 0; i < 16; i++) acc[i] = 0.0f;

    for (int tt = 0; tt < TCHUNK; tt++) {
        const int t = t0 + tt;
        const float* xp = x + ((size_t)(b * NT + t)) * NC * NF;
        __syncthreads();
        for (int i = tid * 4; i < NC * NF; i += 1024) {
            float4 v = *(const float4*)(xp + i);
            float4 s = *(const float4*)(g_sm + i);
            int c = i >> 7, f = i & 127;
            float* dst = &xw[c * 132 + f];
            dst[0] = v.x * s.x; dst[1] = v.y * s.y; dst[2] = v.z * s.z; dst[3] = v.w * s.w;
        }
        __syncthreads();
        // norms (threads 0..63), packed squares
        if (tid < 64) {
            u64 n2 = 0ull;
            const ulonglong2* row = (const ulonglong2*)&xw[tid * 132];
#pragma unroll 8
            for (int f = 0; f < NF / 4; f++) {
                ulonglong2 a = row[f];
                n2 = FFMA2(a.x, a.x, n2);
                n2 = FFMA2(a.y, a.y, n2);
            }
            invn[tid] = 1.0f / (sqrtf(HSUM(n2)) + 1e-8f);
        }
        // Wh (f-packed, no MOVs): thread = (cW, outputs o0..o0+7)
        {
            u64 a[8];
#pragma unroll
            for (int i = 0; i < 8; i++) a[i] = 0ull;
            const ulonglong2* xr = (const ulonglong2*)&xw[cW * 132];
            for (int fc = 0; fc < NF / 4; fc++) {
                ulonglong2 xv = xr[fc];
#pragma unroll
                for (int jj = 0; jj < 8; jj++) {
                    ulonglong2 wv = *(const ulonglong2*)&swT[(o0 + jj) * 132 + fc * 4];
                    a[jj] = FFMA2(xv.x, wv.x, a[jj]);
                    a[jj] = FFMA2(xv.y, wv.y, a[jj]);
                }
            }
            float wa[8];
#pragma unroll
            for (int jj = 0; jj < 8; jj++) wa[jj] = HSUM(a[jj]);
            // transposed store: g_Wh[bt][j][c]
            float* whp = g_Wh + ((size_t)(b * NT + t) * NGO + o0) * NC + cW;
#pragma unroll
            for (int jj = 0; jj < 8; jj++) whp[jj * NC] = wa[jj];
            float p1 = 0.0f, p2 = 0.0f;
#pragma unroll
            for (int jj = 0; jj < 8; jj++) {
                p1 += wa[jj] * __ldg(&gata[o0 + jj]);
                p2 += wa[jj] * __ldg(&gata[NGO + o0 + jj]);
            }
            p1 += __shfl_xor_sync(0xffffffffu, p1, 1);
            p1 += __shfl_xor_sync(0xffffffffu, p1, 2);
            p2 += __shfl_xor_sync(0xffffffffu, p2, 1);
            p2 += __shfl_xor_sync(0xffffffffu, p2, 2);
            if (q == 0) {
                g_s1[(size_t)(b * NT + t) * NC + cW] = p1;
                g_s2[(size_t)(b * NT + t) * NC + cW] = p2;
            }
        }
        __syncthreads();
        // Gram tile, ulonglong2 loads (zero MOVs)
        if (ci >= 0) {
            u64 tm2[16];
#pragma unroll
            for (int i = 0; i < 16; i++) tm2[i] = 0ull;
            for (int k = 0; k < NF; k += 4) {
                ulonglong2 A0 = *(const ulonglong2*)&xw[(r0 + 0) * 132 + k];
                ulonglong2 A1 = *(const ulonglong2*)&xw[(r0 + 1) * 132 + k];
                ulonglong2 A2 = *(const ulonglong2*)&xw[(r0 + 2) * 132 + k];
                ulonglong2 A3 = *(const ulonglong2*)&xw[(r0 + 3) * 132 + k];
                ulonglong2 B0 = *(const ulonglong2*)&xw[(c0 + 0) * 132 + k];
                ulonglong2 B1 = *(const ulonglong2*)&xw[(c0 + 1) * 132 + k];
                ulonglong2 B2 = *(const ulonglong2*)&xw[(c0 + 2) * 132 + k];
                ulonglong2 B3 = *(const ulonglong2*)&xw[(c0 + 3) * 132 + k];
#define GP(IDX, AV, BV) \
    tm2[IDX] = FFMA2(AV.x, BV.x, tm2[IDX]); \
    tm2[IDX] = FFMA2(AV.y, BV.y, tm2[IDX]);
                GP(0,  A0, B0) GP(1,  A0, B1) GP(2,  A0, B2) GP(3,  A0, B3)
                GP(4,  A1, B0) GP(5,  A1, B1) GP(6,  A1, B2) GP(7,  A1, B3)
                GP(8,  A2, B0) GP(9,  A2, B1) GP(10, A2, B2) GP(11, A2, B3)
                GP(12, A3, B0) GP(13, A3, B1) GP(14, A3, B2) GP(15, A3, B3)
#undef GP
            }
            float ir[4], ic[4];
#pragma unroll
            for (int i = 0; i < 4; i++) { ir[i] = invn[r0 + i]; ic[i] = invn[c0 + i]; }
#pragma unroll
            for (int r = 0; r < 4; r++)
#pragma unroll
                for (int cc = 0; cc < 4; cc++)
                    acc[r * 4 + cc] += HSUM(tm2[r * 4 + cc]) * ir[r] * ic[cc];
        }
    }
    if (ci >= 0) {
        float* Ab = g_A + b * NC * NC;
#pragma unroll
        for (int r = 0; r < 4; r++)
#pragma unroll
            for (int cc = 0; cc < 4; cc++) {
                float v = acc[r * 4 + cc];
                atomicAdd(&Ab[(r0 + r) * NC + (c0 + cc)], v);
                if (ci != di) atomicAdd(&Ab[(c0 + cc) * NC + (r0 + r)], v);
            }
    }
}

// ---------------- kernel 2a: per-row top-4 via warp argmax ----------------
__global__ void k2a() {
    int warp = blockIdx.x * 8 + (threadIdx.x >> 5);
    int b = warp >> 6, row = warp & 63;
    int lane = threadIdx.x & 31;
    const float* Ar = g_A + ((size_t)b * NC + row) * NC;
    float v0 = Ar[lane], v1 = Ar[lane + 32];
    u64 mask = 0ull;
#pragma unroll
    for (int r = 0; r < 4; r++) {
        float best; int bi;
        if (v1 > v0) { best = v1; bi = lane + 32; } else { best = v0; bi = lane; }
#pragma unroll
        for (int o = 16; o; o >>= 1) {
            float ov = __shfl_xor_sync(0xffffffffu, best, o);
            int oi = __shfl_xor_sync(0xffffffffu, bi, o);
            if (ov > best || (ov == best && oi < bi)) { best = ov; bi = oi; }
        }
        mask |= 1ull << bi;
        if (bi == lane) v0 = -3.4e38f;
        if (bi == lane + 32) v1 = -3.4e38f;
    }
    mask &= ~(1ull << row);
    if (lane == 0) g_um[b * NC + row] = mask;
}

// ---------------- kernel 2b: build amask ----------------
__global__ void k2b() {
    __shared__ u64 um[NC];
    const int b = blockIdx.x, tid = threadIdx.x;
    if (tid < NC) um[tid] = g_um[b * NC + tid];
    __syncthreads();
    const float* Ab = g_A + (size_t)b * NC * NC;
    unsigned char* amp = g_amask + (size_t)b * NC * NC;
#pragma unroll
    for (int i = tid; i < NC * NC; i += 1024) {
        int c = i >> 6, d = i & 63;
        bool tk = (((um[c] >> d) | (um[d] >> c)) & 1ull) != 0;
        amp[i] = ((tk && Ab[i] > 0.0f) || (c == d)) ? 1 : 0;
    }
}

// ---------------- kernel 3: GAT attention + node pooling ----------------
__global__ void __launch_bounds__(256) k3(const float* __restrict__ pool_w,
                                          const float* __restrict__ pool_b) {
    __shared__ __align__(16) float sWhT[NGO * 68];  // [j][c], pad 68
    __shared__ __align__(16) float sp[NC * 68];     // exp(e-max), pad 68
    __shared__ float sgat[NC * 33];
    __shared__ float ss1[NC], ss2[NC], rinv[NC], pnum[NC];
    __shared__ float pw[NGO];
    __shared__ unsigned int samw[NC * NC / 4];
    unsigned char* sam = (unsigned char*)samw;

    const int bt = blockIdx.x;
    const int b = bt >> 8;
    const int tid = threadIdx.x;

    const float* whp = g_Wh + (size_t)bt * NGO * NC;   // [j][c]
    for (int i = tid; i < NGO * NC; i += 256) sWhT[(i >> 6) * 68 + (i & 63)] = whp[i];
    if (tid < NC) {
        ss1[tid] = g_s1[(size_t)bt * NC + tid];
        ss2[tid] = g_s2[(size_t)bt * NC + tid];
    }
    const unsigned int* amp = (const unsigned int*)(g_amask + (size_t)b * NC * NC);
    for (int i = tid; i < NC * NC / 4; i += 256) samw[i] = amp[i];
    if (tid < NGO) pw[tid] = pool_w[tid];
    __syncthreads();

    const int c = tid >> 2, q = tid & 3, d0 = q * 16;
    float ev[16];
    float m = -3.4e38f;
    const float s1c = ss1[c];
#pragma unroll
    for (int i = 0; i < 16; i++) {
        int d = d0 + i;
        float e = s1c + ss2[d];
        e = (e >= 0.0f) ? e : 0.2f * e;
        if (!sam[c * NC + d]) e = -1e9f;
        ev[i] = e;
        m = fmaxf(m, e);
    }
    m = fmaxf(m, __shfl_xor_sync(0xffffffffu, m, 1));
    m = fmaxf(m, __shfl_xor_sync(0xffffffffu, m, 2));
    float s = 0.0f;
#pragma unroll
    for (int i = 0; i < 16; i++) {
        float p = __expf(ev[i] - m);
        sp[c * 68 + d0 + i] = p;
        s += p;
    }
    s += __shfl_xor_sync(0xffffffffu, s, 1);
    s += __shfl_xor_sync(0xffffffffu, s, 2);
    if (q == 0) rinv[c] = 1.0f / s;
    __syncthreads();

    // phase B: d-packed alpha @ Wh via transposed tile (no MOVs)
    const int o0 = q * 8;
    u64 aj[8];
#pragma unroll
    for (int i = 0; i < 8; i++) aj[i] = 0ull;
    for (int dc = 0; dc < NC; dc += 4) {
        ulonglong2 av = *(const ulonglong2*)&sp[c * 68 + dc];
#pragma unroll
        for (int jj = 0; jj < 8; jj++) {
            ulonglong2 wv = *(const ulonglong2*)&sWhT[(o0 + jj) * 68 + dc];
            aj[jj] = FFMA2(av.x, wv.x, aj[jj]);
            aj[jj] = FFMA2(av.y, wv.y, aj[jj]);
        }
    }
    const float ri = rinv[c];
#pragma unroll
    for (int jj = 0; jj < 8; jj++) {
        float g = HSUM(aj[jj]) * ri;
        sgat[c * 33 + o0 + jj] = (g > 0.0f) ? g : 0.0f;
    }
    __syncthreads();

    if (tid < NC) {
        float p = pool_b[0];
#pragma unroll
        for (int o = 0; o < NGO; o++) p += sgat[tid * 33 + o] * pw[o];
        pnum[tid] = p;
    }
    __syncthreads();
    if (tid < 32) {
        float a0 = pnum[tid], a1 = pnum[tid + 32];
        float mx = fmaxf(a0, a1);
#pragma unroll
        for (int o = 16; o; o >>= 1) mx = fmaxf(mx, __shfl_xor_sync(0xffffffffu, mx, o));
        float e0 = __expf(a0 - mx), e1 = __expf(a1 - mx);
        float sm = e0 + e1;
#pragma unroll
        for (int o = 16; o; o >>= 1) sm += __shfl_xor_sync(0xffffffffu, sm, o);
        pnum[tid] = e0 / sm;
        pnum[tid + 32] = e1 / sm;
    }
    __syncthreads();
    if (tid < NGO) {
        float hv = 0.0f;
#pragma unroll 4
        for (int c2 = 0; c2 < NC; c2++) hv += sgat[c2 * 33 + tid] * pnum[c2];
        g_hp[(size_t)bt * NH + tid] = hv;
    }
}

// ---------------- kernel 4a: LSTM input gates, Wi cached in smem ----------------
__global__ void __launch_bounds__(128) k4a(const float* __restrict__ Wi_f,
                                           const float* __restrict__ b_f,
                                           const float* __restrict__ Wi_r,
                                           const float* __restrict__ b_r) {
    // grid 512: dir = blk>>8, group of 16 bt
    __shared__ float sWi[NH * 128];   // 16 KB
    __shared__ float hs[16 * NH];     // 2 KB
    const int dir = blockIdx.x >> 8;
    const int grp = blockIdx.x & 255;
    const int bt0 = grp * 16;
    const int tid = threadIdx.x;
    const float* Wi = dir ? Wi_r : Wi_f;
    const float* bias = dir ? b_r : b_f;
    for (int i = tid; i < NH * 128; i += 128) sWi[i] = Wi[i];
    for (int i = tid; i < 16 * NH; i += 128) hs[i] = g_hp[(size_t)bt0 * NH + i];
    const float bj = bias[tid];
    __syncthreads();
    float* gxo = g_gx + ((size_t)dir * 4096 + bt0) * 128 + tid;
#pragma unroll 4
    for (int r = 0; r < 16; r++) {
        float a = bj;
#pragma unroll
        for (int k = 0; k < NH; k++) a += hs[r * NH + k] * sWi[k * 128 + tid];
        gxo[r * 128] = a;
    }
}

// ---------------- kernel 4b: LSTM recurrence (1 warp, k-packed gates) ----------------
__global__ void __launch_bounds__(32) k4b(const float* __restrict__ Wh_f,
                                          const float* __restrict__ Wh_r) {
    const int dir = blockIdx.x >> 4;
    const int b = blockIdx.x & 15;
    const float* Wh = dir ? Wh_r : Wh_f;
    const int j = threadIdx.x;
    u64 wi[16], wf[16], wg[16], wo[16];
#pragma unroll
    for (int kp = 0; kp < 16; kp++) {
        const float* ra = Wh + (2 * kp) * 128;
        const float* rb = Wh + (2 * kp + 1) * 128;
        wi[kp] = PK(ra[j],      rb[j]);
        wf[kp] = PK(ra[j + 32], rb[j + 32]);
        wg[kp] = PK(ra[j + 64], rb[j + 64]);
        wo[kp] = PK(ra[j + 96], rb[j + 96]);
    }
    const float* gx = g_gx + ((size_t)dir * 4096 + b * NT) * 128;
    float h = 0.0f, cst = 0.0f;
    int t = dir ? (NT - 1) : 0;
    const int st = dir ? -1 : 1;
    const float* g0p = gx + t * 128;
    float c0 = g0p[j], c1 = g0p[j + 32], c2 = g0p[j + 64], c3 = g0p[j + 96];
    for (int s = 0; s < NT; s++) {
        const int tn = t + st;
        float n0 = 0.0f, n1 = 0.0f, n2 = 0.0f, n3 = 0.0f;
        if (s < NT - 1) {
            const float* gn = gx + tn * 128;
            n0 = gn[j]; n1 = gn[j + 32]; n2 = gn[j + 64]; n3 = gn[j + 96];
        }
        u64 ai = 0ull, af = 0ull, ag = 0ull, ao = 0ull;
#pragma unroll
        for (int kp = 0; kp < 16; kp++) {
            float h0 = __shfl_sync(0xffffffffu, h, 2 * kp);
            float h1 = __shfl_sync(0xffffffffu, h, 2 * kp + 1);
            u64 hp = PK(h0, h1);
            ai = FFMA2(hp, wi[kp], ai);
            af = FFMA2(hp, wf[kp], af);
            ag = FFMA2(hp, wg[kp], ag);
            ao = FFMA2(hp, wo[kp], ao);
        }
        float gi = c0 + HSUM(ai), gf = c1 + HSUM(af);
        float gg = c2 + HSUM(ag), go = c3 + HSUM(ao);
        float ig = fast_sig(gi), fg = fast_sig(gf), og = fast_sig(go);
        cst = fg * cst + ig * fast_tanh(gg);
        h = og * fast_tanh(cst);
        g_hl[(size_t)(b * NT + t) * 64 + dir * NH + j] = h;
        c0 = n0; c1 = n1; c2 = n2; c3 = n3;
        t = tn;
    }
}

// ---------------- kernel 5a: temporal attention scores ----------------
__global__ void k5a(const float* __restrict__ taW, const float* __restrict__ tab,
                    const float* __restrict__ tav) {
    __shared__ __align__(16) float sWt[64 * 68];
    __shared__ float stb[64], stv[64];
    const int tid = threadIdx.x;
    for (int i = tid; i < 4096; i += 64) {
        int k = i >> 6, jj = i & 63;
        sWt[jj * 68 + k] = taW[i];
    }
    if (tid < 64) { stb[tid] = tab[tid]; stv[tid] = tav[tid]; }
    __syncthreads();
    const int b = blockIdx.x >> 2;
    const int t = (blockIdx.x & 3) * 64 + tid;
    const float* hp = g_hl + (size_t)(b * NT + t) * 64;
    float h[64];
#pragma unroll
    for (int k = 0; k < 64; k += 4) {
        float4 v = *(const float4*)(hp + k);
        h[k] = v.x; h[k + 1] = v.y; h[k + 2] = v.z; h[k + 3] = v.w;
    }
    float sc = 0.0f;
    for (int jj = 0; jj < 64; jj++) {
        u64 a0 = PK(stb[jj], 0.0f), a1 = 0ull;
        const float* wr = &sWt[jj * 68];
#pragma unroll
        for (int k = 0; k < 64; k += 4) {
            ulonglong2 wv = *(const ulonglong2*)&wr[k];
            a0 = FFMA2(PK(h[k], h[k + 1]), wv.x, a0);
            a1 = FFMA2(PK(h[k + 2], h[k + 3]), wv.y, a1);
        }
        sc += fast_tanh(HSUM(a0) + HSUM(a1)) * stv[jj];
    }
    g_sc[b * NT + t] = sc * (1.0f / 1.5f);
}

// ---------------- kernel 5b: softmax + ctx + LN + MLP head ----------------
__global__ void k5b(const float* __restrict__ lng, const float* __restrict__ lnb,
                    const float* __restrict__ f1w, const float* __restrict__ f1b,
                    const float* __restrict__ f2w, const float* __restrict__ f2b,
                    float* __restrict__ out) {
    const int b = blockIdx.x, t = threadIdx.x;
    __shared__ float sal[NT];
    __shared__ float wr[8];
    __shared__ float part[4][64];
    __shared__ float ctxs[64];
    __shared__ float y1s[32];
    __shared__ float stats[2];
    float sc = g_sc[b * NT + t];
    const int lane = t & 31, w = t >> 5;
    float m = sc;
#pragma unroll
    for (int o = 16; o; o >>= 1) m = fmaxf(m, __shfl_xor_sync(0xffffffffu, m, o));
    if (lane == 0) wr[w] = m;
    __syncthreads();
    m = wr[0];
#pragma unroll
    for (int i = 1; i < 8; i++) m = fmaxf(m, wr[i]);
    float e = __expf(sc - m);
    float s = e;
#pragma unroll
    for (int o = 16; o; o >>= 1) s += __shfl_xor_sync(0xffffffffu, s, o);
    __syncthreads();
    if (lane == 0) wr[w] = s;
    __syncthreads();
    s = 0.0f;
#pragma unroll
    for (int i = 0; i < 8; i++) s += wr[i];
    sal[t] = e / s;
    __syncthreads();
    {
        const int k = t & 63, q4 = t >> 6;
        float cx = 0.0f;
        const float* hb = g_hl + (size_t)b * NT * 64;
        for (int tt = q4 * 64; tt < q4 * 64 + 64; tt++)
            cx += hb[(size_t)tt * 64 + k] * sal[tt];
        part[q4][k] = cx;
    }
    __syncthreads();
    if (t < 64) ctxs[t] = part[0][t] + part[1][t] + part[2][t] + part[3][t];
    __syncthreads();
    if (t == 0) {
        float mean = 0.0f;
        for (int k = 0; k < 64; k++) mean += ctxs[k];
        mean *= (1.0f / 64.0f);
        float var = 0.0f;
        for (int k = 0; k < 64; k++) { float d2 = ctxs[k] - mean; var += d2 * d2; }
        var *= (1.0f / 64.0f);
        stats[0] = mean;
        stats[1] = rsqrtf(var + 1e-5f);
    }
    __syncthreads();
    if (t < 64) ctxs[t] = (ctxs[t] - stats[0]) * stats[1] * lng[t] + lnb[t];
    __syncthreads();
    if (t < 32) {
        float a = f1b[t];
#pragma unroll
        for (int k = 0; k < 64; k++) a += ctxs[k] * f1w[k * 32 + t];
        y1s[t] = (a > 0.0f) ? a : 0.0f;
    }
    __syncthreads();
    if (t < 3) {
        float o = f2b[t];
#pragma unroll
        for (int m2 = 0; m2 < 32; m2++) o += y1s[m2] * f2w[m2 * 3 + t];
        out[b * 3 + t] = o;
    }
}

// ---------------- launcher ----------------
extern "C" void kernel_launch(void* const* d_in, const int* in_sizes, int n_in,
                              void* d_out, int out_size) {
    const float* x       = (const float*)d_in[0];
    const float* spec_w  = (const float*)d_in[1];
    const float* gat_W   = (const float*)d_in[2];
    const float* gat_a   = (const float*)d_in[3];
    const float* pool_w  = (const float*)d_in[4];
    const float* pool_b  = (const float*)d_in[5];
    const float* Wi_f    = (const float*)d_in[6];
    const float* Wh_f    = (const float*)d_in[7];
    const float* b_f     = (const float*)d_in[8];
    const float* Wi_r    = (const float*)d_in[9];
    const float* Wh_r    = (const float*)d_in[10];
    const float* b_r     = (const float*)d_in[11];
    const float* taW     = (const float*)d_in[12];
    const float* tab     = (const float*)d_in[13];
    const float* tav     = (const float*)d_in[14];
    const float* lng     = (const float*)d_in[15];
    const float* lnb     = (const float*)d_in[16];
    const float* f1w     = (const float*)d_in[17];
    const float* f1b     = (const float*)d_in[18];
    const float* f2w     = (const float*)d_in[19];
    const float* f2b     = (const float*)d_in[20];

    const int k1_smem = (64 * 132 + 32 * 132 + 64) * 4;
    cudaFuncSetAttribute(k1, cudaFuncAttributeMaxDynamicSharedMemorySize, k1_smem);

    k_sm<<<64, 128>>>(spec_w);                       // launch 1
    k_zeroA<<<NB * NC * NC / 512, 256>>>(0);         // launch 2
    k_zeroA<<<NB * NC * NC / 512, 256>>>(1);         // launch 3
    k1<<<NB * (NT / TCHUNK), 256, k1_smem>>>(x, gat_W, gat_a);  // launch 4 <- profiled
    k2a<<<128, 256>>>();
    k2b<<<NB, 1024>>>();
    k3<<<NB * NT, 256>>>(pool_w, pool_b);
    k4a<<<512, 128>>>(Wi_f, b_f, Wi_r, b_r);
    k4b<<<32, 32>>>(Wh_f, Wh_r);
    k5a<<<64, 64>>>(taW, tab, tav);
    k5b<<<NB, 256>>>(lng, lnb, f1w, f1b, f2w, f2b, (float*)d_out);
}

// round 7
// speedup vs baseline: 1.7709x; 1.7709x over previous
#include <cuda_runtime.h>
#include <math.h>

#define NB 16
#define NT 256
#define NC 64
#define NF 128
#define NGO 32
#define NH 32
#define TCHUNK 8
#define XP 34   // u64 row stride for 32-slot paired smem arrays
#define SPS 66  // u64 row stride for 64-slot spP rows in k3

typedef unsigned long long u64;

// ---------------- packed f32x2 helpers ----------------
__device__ __forceinline__ u64 PK(float x, float y) {
    u64 r;
    asm("mov.b64 %0, {%1,%2};" : "=l"(r) : "f"(x), "f"(y));
    return r;
}
__device__ __forceinline__ float2 UPK(u64 v) {
    float2 f;
    asm("mov.b64 {%0,%1}, %2;" : "=f"(f.x), "=f"(f.y) : "l"(v));
    return f;
}
__device__ __forceinline__ u64 FFMA2(u64 a, u64 b, u64 c) {
    u64 d;
    asm("fma.rn.f32x2 %0, %1, %2, %3;" : "=l"(d) : "l"(a), "l"(b), "l"(c));
    return d;
}
__device__ __forceinline__ float HSUM(u64 v) {
    float2 f = UPK(v);
    return f.x + f.y;
}
__device__ __forceinline__ float fast_tanh(float x) {
    float e = __expf(2.0f * x);
    return 1.0f - __fdividef(2.0f, e + 1.0f);
}
__device__ __forceinline__ float fast_sig(float x) {
    return 1.0f / (1.0f + __expf(-x));
}

// ---------------- scratch ----------------
__device__ float g_sm[NC * NF];
__device__ float g_A[NB * NC * NC];
__device__ u64 g_um[NB * NC];
__device__ unsigned char g_amask[NB * NC * NC];
__device__ float g_Wh[NB * NT * NC * NGO];   // [bt][c][j]
__device__ float g_s1[NB * NT * NC];
__device__ float g_s2[NB * NT * NC];
__device__ float g_hp[NB * NT * NH];
__device__ float g_gx[2 * NB * NT * 4 * NH];
__device__ float g_hl[NB * NT * 2 * NH];
__device__ float g_sc[NB * NT];

// ---------------- kernel 0: row softmax of spectral_w ----------------
__global__ void k_sm(const float* __restrict__ sw) {
    int c = blockIdx.x, f = threadIdx.x;
    float v = sw[c * NF + f];
    __shared__ float rm[4], rs[4];
    int lane = f & 31, w = f >> 5;
    float m = v;
#pragma unroll
    for (int o = 16; o; o >>= 1) m = fmaxf(m, __shfl_xor_sync(0xffffffffu, m, o));
    if (lane == 0) rm[w] = m;
    __syncthreads();
    m = fmaxf(fmaxf(rm[0], rm[1]), fmaxf(rm[2], rm[3]));
    float e = __expf(v - m);
    float s = e;
#pragma unroll
    for (int o = 16; o; o >>= 1) s += __shfl_xor_sync(0xffffffffu, s, o);
    if (lane == 0) rs[w] = s;
    __syncthreads();
    s = rs[0] + rs[1] + rs[2] + rs[3];
    g_sm[c * NF + f] = e / s;
}

__global__ void k_zeroA(int half) {
    int i = half * (NB * NC * NC / 2) + blockIdx.x * blockDim.x + threadIdx.x;
    g_A[i] = 0.0f;
}

// ---------------- kernel 1: spectral weight + Gram->A + Wh + s1/s2 ----------------
// Conflict-free layout: xA holds cols c%4 in {0,1}, xB cols c%4 in {2,3},
// both [f2][slot] with row stride XP=34 u64 (272B ≡ 16 mod 128).
extern __shared__ u64 sh1[];
__global__ void __launch_bounds__(256) k1(const float* __restrict__ x,
                                          const float* __restrict__ gatW,
                                          const float* __restrict__ gata) {
    u64* xA  = sh1;                  // [64][XP]
    u64* xB  = sh1 + 64 * XP;        // [64][XP]
    u64* swP = sh1 + 2 * 64 * XP;    // [f2][j] pairs over f
    float* invn = (float*)(sh1 + 3 * 64 * XP);

    const int b  = blockIdx.x >> 5;
    const int t0 = (blockIdx.x & 31) * TCHUNK;
    const int tid = threadIdx.x;

    for (int i = tid; i < 64 * NGO; i += 256) {
        int f2 = i >> 5, j = i & 31;
        swP[f2 * XP + j] = PK(gatW[(2 * f2) * NGO + j], gatW[(2 * f2 + 1) * NGO + j]);
    }

    const int ty = tid >> 4, tx = tid & 15;
    const int cW = tid >> 2, q = tid & 3, o0 = q * 8;
    const u64* xs_w = (cW & 2) ? xB : xA;
    const int xoff_w = (cW >> 2) * 2 + (cW & 1);

    float acc[16];
#pragma unroll
    for (int i = 0; i < 16; i++) acc[i] = 0.0f;

    for (int tt = 0; tt < TCHUNK; tt++) {
        const int bt = b * NT + t0 + tt;
        __syncthreads();
        // load x as f-pairs, spectral scale, write into split layout
        {
            const float2* x2 = (const float2*)(x + (size_t)bt * NC * NF);
            const float2* s2 = (const float2*)g_sm;
            for (int i = tid; i < NC * NF / 2; i += 256) {
                int c = i >> 6;
                int f2 = i & 63;
                float2 v = x2[i];
                float2 s = s2[i];
                u64* dst = (c & 2) ? xB : xA;
                dst[f2 * XP + (c >> 2) * 2 + (c & 1)] = PK(v.x * s.x, v.y * s.y);
            }
        }
        __syncthreads();
        // norms
        if (tid < 64) {
            const u64* src = (tid & 2) ? xB : xA;
            const int off = (tid >> 2) * 2 + (tid & 1);
            u64 n2 = 0ull;
#pragma unroll 8
            for (int f2 = 0; f2 < 64; f2++) {
                u64 v = src[f2 * XP + off];
                n2 = FFMA2(v, v, n2);
            }
            invn[tid] = 1.0f / (sqrtf(HSUM(n2)) + 1e-8f);
        }
        // Wh + s1/s2: thread = (cW, j-tile o0..o0+7)
        {
            u64 aj[8];
#pragma unroll
            for (int i = 0; i < 8; i++) aj[i] = 0ull;
#pragma unroll 4
            for (int f2 = 0; f2 < 64; f2++) {
                u64 xv = xs_w[f2 * XP + xoff_w];
                const u64* wrow = &swP[f2 * XP + o0];
                ulonglong2 w0 = *(const ulonglong2*)(wrow);
                ulonglong2 w1 = *(const ulonglong2*)(wrow + 2);
                ulonglong2 w2 = *(const ulonglong2*)(wrow + 4);
                ulonglong2 w3 = *(const ulonglong2*)(wrow + 6);
                aj[0] = FFMA2(xv, w0.x, aj[0]);
                aj[1] = FFMA2(xv, w0.y, aj[1]);
                aj[2] = FFMA2(xv, w1.x, aj[2]);
                aj[3] = FFMA2(xv, w1.y, aj[3]);
                aj[4] = FFMA2(xv, w2.x, aj[4]);
                aj[5] = FFMA2(xv, w2.y, aj[5]);
                aj[6] = FFMA2(xv, w3.x, aj[6]);
                aj[7] = FFMA2(xv, w3.y, aj[7]);
            }
            float wa[8];
#pragma unroll
            for (int jj = 0; jj < 8; jj++) wa[jj] = HSUM(aj[jj]);
            float* whp = g_Wh + (size_t)bt * NC * NGO + cW * NGO + o0;
            *(float4*)whp       = make_float4(wa[0], wa[1], wa[2], wa[3]);
            *(float4*)(whp + 4) = make_float4(wa[4], wa[5], wa[6], wa[7]);
            float p1 = 0.0f, p2 = 0.0f;
#pragma unroll
            for (int jj = 0; jj < 8; jj++) {
                p1 += wa[jj] * __ldg(&gata[o0 + jj]);
                p2 += wa[jj] * __ldg(&gata[NGO + o0 + jj]);
            }
            p1 += __shfl_xor_sync(0xffffffffu, p1, 1);
            p1 += __shfl_xor_sync(0xffffffffu, p1, 2);
            p2 += __shfl_xor_sync(0xffffffffu, p2, 1);
            p2 += __shfl_xor_sync(0xffffffffu, p2, 2);
            if (q == 0) {
                g_s1[(size_t)bt * NC + cW] = p1;
                g_s2[(size_t)bt * NC + cW] = p2;
            }
        }
        __syncthreads();   // invn visible
        // Gram: full 64x64, thread tile 4x4, conflict-free loads
        {
            u64 P[16];
#pragma unroll
            for (int i = 0; i < 16; i++) P[i] = 0ull;
#pragma unroll 2
            for (int f2 = 0; f2 < 64; f2++) {
                const int base = f2 * XP;
                ulonglong2 aA = *(const ulonglong2*)&xA[base + ty * 2];
                ulonglong2 aB = *(const ulonglong2*)&xB[base + ty * 2];
                ulonglong2 bA = *(const ulonglong2*)&xA[base + tx * 2];
                ulonglong2 bB = *(const ulonglong2*)&xB[base + tx * 2];
                u64 ar0 = aA.x, ar1 = aA.y, ar2 = aB.x, ar3 = aB.y;
                u64 bc0 = bA.x, bc1 = bA.y, bc2 = bB.x, bc3 = bB.y;
                P[0]  = FFMA2(ar0, bc0, P[0]);  P[1]  = FFMA2(ar0, bc1, P[1]);
                P[2]  = FFMA2(ar0, bc2, P[2]);  P[3]  = FFMA2(ar0, bc3, P[3]);
                P[4]  = FFMA2(ar1, bc0, P[4]);  P[5]  = FFMA2(ar1, bc1, P[5]);
                P[6]  = FFMA2(ar1, bc2, P[6]);  P[7]  = FFMA2(ar1, bc3, P[7]);
                P[8]  = FFMA2(ar2, bc0, P[8]);  P[9]  = FFMA2(ar2, bc1, P[9]);
                P[10] = FFMA2(ar2, bc2, P[10]); P[11] = FFMA2(ar2, bc3, P[11]);
                P[12] = FFMA2(ar3, bc0, P[12]); P[13] = FFMA2(ar3, bc1, P[13]);
                P[14] = FFMA2(ar3, bc2, P[14]); P[15] = FFMA2(ar3, bc3, P[15]);
            }
            float ir[4], ic[4];
#pragma unroll
            for (int i = 0; i < 4; i++) {
                ir[i] = invn[ty * 4 + i];
                ic[i] = invn[tx * 4 + i];
            }
#pragma unroll
            for (int r = 0; r < 4; r++)
#pragma unroll
                for (int c = 0; c < 4; c++)
                    acc[r * 4 + c] += HSUM(P[r * 4 + c]) * ir[r] * ic[c];
        }
    }
    {
        float* Ab = g_A + b * NC * NC;
#pragma unroll
        for (int r = 0; r < 4; r++)
#pragma unroll
            for (int c = 0; c < 4; c++)
                atomicAdd(&Ab[(ty * 4 + r) * NC + tx * 4 + c], acc[r * 4 + c]);
    }
}

// ---------------- kernel 2a: per-row top-4 via warp argmax ----------------
__global__ void k2a() {
    int warp = blockIdx.x * 8 + (threadIdx.x >> 5);
    int b = warp >> 6, row = warp & 63;
    int lane = threadIdx.x & 31;
    const float* Ar = g_A + ((size_t)b * NC + row) * NC;
    float v0 = Ar[lane], v1 = Ar[lane + 32];
    u64 mask = 0ull;
#pragma unroll
    for (int r = 0; r < 4; r++) {
        float best; int bi;
        if (v1 > v0) { best = v1; bi = lane + 32; } else { best = v0; bi = lane; }
#pragma unroll
        for (int o = 16; o; o >>= 1) {
            float ov = __shfl_xor_sync(0xffffffffu, best, o);
            int oi = __shfl_xor_sync(0xffffffffu, bi, o);
            if (ov > best || (ov == best && oi < bi)) { best = ov; bi = oi; }
        }
        mask |= 1ull << bi;
        if (bi == lane) v0 = -3.4e38f;
        if (bi == lane + 32) v1 = -3.4e38f;
    }
    mask &= ~(1ull << row);
    if (lane == 0) g_um[b * NC + row] = mask;
}

// ---------------- kernel 2b: build amask ----------------
__global__ void k2b() {
    __shared__ u64 um[NC];
    const int b = blockIdx.x, tid = threadIdx.x;
    if (tid < NC) um[tid] = g_um[b * NC + tid];
    __syncthreads();
    const float* Ab = g_A + (size_t)b * NC * NC;
    unsigned char* amp = g_amask + (size_t)b * NC * NC;
#pragma unroll
    for (int i = tid; i < NC * NC; i += 1024) {
        int c = i >> 6, d = i & 63;
        bool tk = (((um[c] >> d) | (um[d] >> c)) & 1ull) != 0;
        amp[i] = ((tk && Ab[i] > 0.0f) || (c == d)) ? 1 : 0;
    }
}

// ---------------- kernel 3: GAT attention + node pooling ----------------
__global__ void __launch_bounds__(256) k3(const float* __restrict__ pool_w,
                                          const float* __restrict__ pool_b) {
    __shared__ __align__(16) u64 spP[32 * SPS];  // [d2][c]: (exp[c][2d2],exp[c][2d2+1])
    __shared__ __align__(16) u64 whP[32 * XP];   // [d2][j]: (Wh[2d2][j],Wh[2d2+1][j])
    __shared__ float sgat[NC * 33];
    __shared__ float ss1[NC], ss2[NC], rinv[NC], pnum[NC];
    __shared__ float pw[NGO];
    __shared__ unsigned int samw[NC * NC / 4];
    unsigned char* sam = (unsigned char*)samw;

    const int bt = blockIdx.x;
    const int b = bt >> 8;
    const int tid = threadIdx.x;

    const float* whg = g_Wh + (size_t)bt * NC * NGO;
    for (int i = tid; i < 32 * 32; i += 256) {
        int d2 = i >> 5, j = i & 31;
        whP[d2 * XP + j] = PK(whg[(2 * d2) * NGO + j], whg[(2 * d2 + 1) * NGO + j]);
    }
    if (tid < NC) {
        ss1[tid] = g_s1[(size_t)bt * NC + tid];
        ss2[tid] = g_s2[(size_t)bt * NC + tid];
    }
    const unsigned int* amp = (const unsigned int*)(g_amask + (size_t)b * NC * NC);
    for (int i = tid; i < NC * NC / 4; i += 256) samw[i] = amp[i];
    if (tid < NGO) pw[tid] = pool_w[tid];
    __syncthreads();

    const int c = tid >> 2, q = tid & 3, d0 = q * 16;
    // phase A: masked row softmax (4 threads/row), store exp pairs into spP
    float ev[16];
    float m = -3.4e38f;
    const float s1c = ss1[c];
#pragma unroll
    for (int i = 0; i < 16; i++) {
        int d = d0 + i;
        float e = s1c + ss2[d];
        e = (e >= 0.0f) ? e : 0.2f * e;
        if (!sam[c * NC + d]) e = -1e9f;
        ev[i] = e;
        m = fmaxf(m, e);
    }
    m = fmaxf(m, __shfl_xor_sync(0xffffffffu, m, 1));
    m = fmaxf(m, __shfl_xor_sync(0xffffffffu, m, 2));
    float s = 0.0f;
#pragma unroll
    for (int i = 0; i < 16; i++) {
        ev[i] = __expf(ev[i] - m);
        s += ev[i];
    }
#pragma unroll
    for (int k = 0; k < 8; k++)
        spP[(q * 8 + k) * SPS + c] = PK(ev[2 * k], ev[2 * k + 1]);
    s += __shfl_xor_sync(0xffffffffu, s, 1);
    s += __shfl_xor_sync(0xffffffffu, s, 2);
    if (q == 0) rinv[c] = 1.0f / s;
    __syncthreads();

    // phase B: alpha @ Wh, thread tile 4 rows x 2 cols, conflict-free
    {
        const int ty = tid >> 4, tx = tid & 15;
        const int r0 = 4 * ty, j0 = 2 * tx;
        u64 P[8];
#pragma unroll
        for (int i = 0; i < 8; i++) P[i] = 0ull;
#pragma unroll 2
        for (int d2 = 0; d2 < 32; d2++) {
            ulonglong2 a01 = *(const ulonglong2*)&spP[d2 * SPS + r0];
            ulonglong2 a23 = *(const ulonglong2*)&spP[d2 * SPS + r0 + 2];
            ulonglong2 bb  = *(const ulonglong2*)&whP[d2 * XP + j0];
            P[0] = FFMA2(a01.x, bb.x, P[0]); P[1] = FFMA2(a01.x, bb.y, P[1]);
            P[2] = FFMA2(a01.y, bb.x, P[2]); P[3] = FFMA2(a01.y, bb.y, P[3]);
            P[4] = FFMA2(a23.x, bb.x, P[4]); P[5] = FFMA2(a23.x, bb.y, P[5]);
            P[6] = FFMA2(a23.y, bb.x, P[6]); P[7] = FFMA2(a23.y, bb.y, P[7]);
        }
#pragma unroll
        for (int r = 0; r < 4; r++) {
            float ri = rinv[r0 + r];
#pragma unroll
            for (int jj = 0; jj < 2; jj++) {
                float g = HSUM(P[r * 2 + jj]) * ri;
                sgat[(r0 + r) * 33 + j0 + jj] = (g > 0.0f) ? g : 0.0f;
            }
        }
    }
    __syncthreads();

    // pooling
    if (tid < NC) {
        float p = pool_b[0];
#pragma unroll
        for (int o = 0; o < NGO; o++) p += sgat[tid * 33 + o] * pw[o];
        pnum[tid] = p;
    }
    __syncthreads();
    if (tid < 32) {
        float a0 = pnum[tid], a1 = pnum[tid + 32];
        float mx = fmaxf(a0, a1);
#pragma unroll
        for (int o = 16; o; o >>= 1) mx = fmaxf(mx, __shfl_xor_sync(0xffffffffu, mx, o));
        float e0 = __expf(a0 - mx), e1 = __expf(a1 - mx);
        float sm = e0 + e1;
#pragma unroll
        for (int o = 16; o; o >>= 1) sm += __shfl_xor_sync(0xffffffffu, sm, o);
        pnum[tid] = e0 / sm;
        pnum[tid + 32] = e1 / sm;
    }
    __syncthreads();
    if (tid < NGO) {
        float hv = 0.0f;
#pragma unroll 4
        for (int c2 = 0; c2 < NC; c2++) hv += sgat[c2 * 33 + tid] * pnum[c2];
        g_hp[(size_t)bt * NH + tid] = hv;
    }
}

// ---------------- kernel 4a: LSTM input gates, Wi cached in smem ----------------
__global__ void __launch_bounds__(128) k4a(const float* __restrict__ Wi_f,
                                           const float* __restrict__ b_f,
                                           const float* __restrict__ Wi_r,
                                           const float* __restrict__ b_r) {
    __shared__ float sWi[NH * 128];
    __shared__ float hs[16 * NH];
    const int dir = blockIdx.x >> 8;
    const int grp = blockIdx.x & 255;
    const int bt0 = grp * 16;
    const int tid = threadIdx.x;
    const float* Wi = dir ? Wi_r : Wi_f;
    const float* bias = dir ? b_r : b_f;
    for (int i = tid; i < NH * 128; i += 128) sWi[i] = Wi[i];
    for (int i = tid; i < 16 * NH; i += 128) hs[i] = g_hp[(size_t)bt0 * NH + i];
    const float bj = bias[tid];
    __syncthreads();
    float* gxo = g_gx + ((size_t)dir * 4096 + bt0) * 128 + tid;
#pragma unroll 4
    for (int r = 0; r < 16; r++) {
        float a = bj;
#pragma unroll
        for (int k = 0; k < NH; k++) a += hs[r * NH + k] * sWi[k * 128 + tid];
        gxo[r * 128] = a;
    }
}

// ---------------- kernel 4b: LSTM recurrence (1 warp, k-packed gates) ----------------
__global__ void __launch_bounds__(32) k4b(const float* __restrict__ Wh_f,
                                          const float* __restrict__ Wh_r) {
    const int dir = blockIdx.x >> 4;
    const int b = blockIdx.x & 15;
    const float* Wh = dir ? Wh_r : Wh_f;
    const int j = threadIdx.x;
    u64 wi[16], wf[16], wg[16], wo[16];
#pragma unroll
    for (int kp = 0; kp < 16; kp++) {
        const float* ra = Wh + (2 * kp) * 128;
        const float* rb = Wh + (2 * kp + 1) * 128;
        wi[kp] = PK(ra[j],      rb[j]);
        wf[kp] = PK(ra[j + 32], rb[j + 32]);
        wg[kp] = PK(ra[j + 64], rb[j + 64]);
        wo[kp] = PK(ra[j + 96], rb[j + 96]);
    }
    const float* gx = g_gx + ((size_t)dir * 4096 + b * NT) * 128;
    float h = 0.0f, cst = 0.0f;
    int t = dir ? (NT - 1) : 0;
    const int st = dir ? -1 : 1;
    const float* g0p = gx + t * 128;
    float c0 = g0p[j], c1 = g0p[j + 32], c2 = g0p[j + 64], c3 = g0p[j + 96];
    for (int s = 0; s < NT; s++) {
        const int tn = t + st;
        float n0 = 0.0f, n1 = 0.0f, n2 = 0.0f, n3 = 0.0f;
        if (s < NT - 1) {
            const float* gn = gx + tn * 128;
            n0 = gn[j]; n1 = gn[j + 32]; n2 = gn[j + 64]; n3 = gn[j + 96];
        }
        u64 ai = 0ull, af = 0ull, ag = 0ull, ao = 0ull;
#pragma unroll
        for (int kp = 0; kp < 16; kp++) {
            float h0 = __shfl_sync(0xffffffffu, h, 2 * kp);
            float h1 = __shfl_sync(0xffffffffu, h, 2 * kp + 1);
            u64 hp = PK(h0, h1);
            ai = FFMA2(hp, wi[kp], ai);
            af = FFMA2(hp, wf[kp], af);
            ag = FFMA2(hp, wg[kp], ag);
            ao = FFMA2(hp, wo[kp], ao);
        }
        float gi = c0 + HSUM(ai), gf = c1 + HSUM(af);
        float gg = c2 + HSUM(ag), go = c3 + HSUM(ao);
        float ig = fast_sig(gi), fg = fast_sig(gf), og = fast_sig(go);
        cst = fg * cst + ig * fast_tanh(gg);
        h = og * fast_tanh(cst);
        g_hl[(size_t)(b * NT + t) * 64 + dir * NH + j] = h;
        c0 = n0; c1 = n1; c2 = n2; c3 = n3;
        t = tn;
    }
}

// ---------------- kernel 5a: temporal attention scores ----------------
__global__ void k5a(const float* __restrict__ taW, const float* __restrict__ tab,
                    const float* __restrict__ tav) {
    __shared__ __align__(16) float sWt[64 * 68];
    __shared__ float stb[64], stv[64];
    const int tid = threadIdx.x;
    for (int i = tid; i < 4096; i += 64) {
        int k = i >> 6, jj = i & 63;
        sWt[jj * 68 + k] = taW[i];
    }
    if (tid < 64) { stb[tid] = tab[tid]; stv[tid] = tav[tid]; }
    __syncthreads();
    const int b = blockIdx.x >> 2;
    const int t = (blockIdx.x & 3) * 64 + tid;
    const float* hp = g_hl + (size_t)(b * NT + t) * 64;
    float h[64];
#pragma unroll
    for (int k = 0; k < 64; k += 4) {
        float4 v = *(const float4*)(hp + k);
        h[k] = v.x; h[k + 1] = v.y; h[k + 2] = v.z; h[k + 3] = v.w;
    }
    float sc = 0.0f;
    for (int jj = 0; jj < 64; jj++) {
        u64 a0 = PK(stb[jj], 0.0f), a1 = 0ull;
        const float* wr = &sWt[jj * 68];
#pragma unroll
        for (int k = 0; k < 64; k += 4) {
            ulonglong2 wv = *(const ulonglong2*)&wr[k];
            a0 = FFMA2(PK(h[k], h[k + 1]), wv.x, a0);
            a1 = FFMA2(PK(h[k + 2], h[k + 3]), wv.y, a1);
        }
        sc += fast_tanh(HSUM(a0) + HSUM(a1)) * stv[jj];
    }
    g_sc[b * NT + t] = sc * (1.0f / 1.5f);
}

// ---------------- kernel 5b: softmax + ctx + LN + MLP head ----------------
__global__ void k5b(const float* __restrict__ lng, const float* __restrict__ lnb,
                    const float* __restrict__ f1w, const float* __restrict__ f1b,
                    const float* __restrict__ f2w, const float* __restrict__ f2b,
                    float* __restrict__ out) {
    const int b = blockIdx.x, t = threadIdx.x;
    __shared__ float sal[NT];
    __shared__ float wr[8];
    __shared__ float part[4][64];
    __shared__ float ctxs[64];
    __shared__ float y1s[32];
    __shared__ float stats[2];
    float sc = g_sc[b * NT + t];
    const int lane = t & 31, w = t >> 5;
    float m = sc;
#pragma unroll
    for (int o = 16; o; o >>= 1) m = fmaxf(m, __shfl_xor_sync(0xffffffffu, m, o));
    if (lane == 0) wr[w] = m;
    __syncthreads();
    m = wr[0];
#pragma unroll
    for (int i = 1; i < 8; i++) m = fmaxf(m, wr[i]);
    float e = __expf(sc - m);
    float s = e;
#pragma unroll
    for (int o = 16; o; o >>= 1) s += __shfl_xor_sync(0xffffffffu, s, o);
    __syncthreads();
    if (lane == 0) wr[w] = s;
    __syncthreads();
    s = 0.0f;
#pragma unroll
    for (int i = 0; i < 8; i++) s += wr[i];
    sal[t] = e / s;
    __syncthreads();
    {
        const int k = t & 63, q4 = t >> 6;
        float cx = 0.0f;
        const float* hb = g_hl + (size_t)b * NT * 64;
        for (int tt = q4 * 64; tt < q4 * 64 + 64; tt++)
            cx += hb[(size_t)tt * 64 + k] * sal[tt];
        part[q4][k] = cx;
    }
    __syncthreads();
    if (t < 64) ctxs[t] = part[0][t] + part[1][t] + part[2][t] + part[3][t];
    __syncthreads();
    if (t == 0) {
        float mean = 0.0f;
        for (int k = 0; k < 64; k++) mean += ctxs[k];
        mean *= (1.0f / 64.0f);
        float var = 0.0f;
        for (int k = 0; k < 64; k++) { float d2 = ctxs[k] - mean; var += d2 * d2; }
        var *= (1.0f / 64.0f);
        stats[0] = mean;
        stats[1] = rsqrtf(var + 1e-5f);
    }
    __syncthreads();
    if (t < 64) ctxs[t] = (ctxs[t] - stats[0]) * stats[1] * lng[t] + lnb[t];
    __syncthreads();
    if (t < 32) {
        float a = f1b[t];
#pragma unroll
        for (int k = 0; k < 64; k++) a += ctxs[k] * f1w[k * 32 + t];
        y1s[t] = (a > 0.0f) ? a : 0.0f;
    }
    __syncthreads();
    if (t < 3) {
        float o = f2b[t];
#pragma unroll
        for (int m2 = 0; m2 < 32; m2++) o += y1s[m2] * f2w[m2 * 3 + t];
        out[b * 3 + t] = o;
    }
}

// ---------------- launcher ----------------
extern "C" void kernel_launch(void* const* d_in, const int* in_sizes, int n_in,
                              void* d_out, int out_size) {
    const float* x       = (const float*)d_in[0];
    const float* spec_w  = (const float*)d_in[1];
    const float* gat_W   = (const float*)d_in[2];
    const float* gat_a   = (const float*)d_in[3];
    const float* pool_w  = (const float*)d_in[4];
    const float* pool_b  = (const float*)d_in[5];
    const float* Wi_f    = (const float*)d_in[6];
    const float* Wh_f    = (const float*)d_in[7];
    const float* b_f     = (const float*)d_in[8];
    const float* Wi_r    = (const float*)d_in[9];
    const float* Wh_r    = (const float*)d_in[10];
    const float* b_r     = (const float*)d_in[11];
    const float* taW     = (const float*)d_in[12];
    const float* tab     = (const float*)d_in[13];
    const float* tav     = (const float*)d_in[14];
    const float* lng     = (const float*)d_in[15];
    const float* lnb     = (const float*)d_in[16];
    const float* f1w     = (const float*)d_in[17];
    const float* f1b     = (const float*)d_in[18];
    const float* f2w     = (const float*)d_in[19];
    const float* f2b     = (const float*)d_in[20];

    const int k1_smem = (3 * 64 * XP) * 8 + 64 * 4;   // 52480 B
    cudaFuncSetAttribute(k1, cudaFuncAttributeMaxDynamicSharedMemorySize, k1_smem);

    k_sm<<<64, 128>>>(spec_w);                       // launch 1
    k_zeroA<<<NB * NC * NC / 512, 256>>>(0);         // launch 2
    k_zeroA<<<NB * NC * NC / 512, 256>>>(1);         // launch 3
    k1<<<NB * (NT / TCHUNK), 256, k1_smem>>>(x, gat_W, gat_a);  // launch 4 <- profiled
    k2a<<<128, 256>>>();
    k2b<<<NB, 1024>>>();
    k3<<<NB * NT, 256>>>(pool_w, pool_b);
    k4a<<<512, 128>>>(Wi_f, b_f, Wi_r, b_r);
    k4b<<<32, 32>>>(Wh_f, Wh_r);
    k5a<<<64, 64>>>(taW, tab, tav);
    k5b<<<NB, 256>>>(lng, lnb, f1w, f1b, f2w, f2b, (float*)d_out);
}